// round 3
// baseline (speedup 1.0000x reference)
#include <cuda_runtime.h>
#include <cuda_bf16.h>
#include <math.h>

// Problem constants (fixed by the dataset)
#define B_   2
#define C_   64
#define E_   4
#define HLR_ 192
#define WLR_ 192
#define SC_  2
#define HHR_ (HLR_*SC_)   // 384
#define WHR_ (WLR_*SC_)   // 384

// Precomputed per-parity quantities (4 variants: hp*2+wp)
__device__ float g_off[2][2][2];        // [hp][wp][{x,y}]
__device__ float g_wc [2][2][8][64];    // dynamic compress weights [hp][wp][j][c]
__device__ float g_we [2][2][64][8];    // dynamic expand weights   [hp][wp][c][j]

// ---------------------------------------------------------------------------
// Kernel 0: compute the 4 parity variants of the MLP outputs and the
// routing-mixed dynamic weights. 1 block, 256 threads.
// ---------------------------------------------------------------------------
__global__ void __launch_bounds__(256) precompute_kernel(
    const float* __restrict__ w1, const float* __restrict__ b1,
    const float* __restrict__ w2, const float* __restrict__ b2,
    const float* __restrict__ rw, const float* __restrict__ rb,
    const float* __restrict__ ow, const float* __restrict__ ob,
    const float* __restrict__ WC, const float* __restrict__ WE)
{
    __shared__ float s_emb[4][64];
    __shared__ float s_rt[4][4];

    int tid = threadIdx.x;
    int v = tid >> 6;        // variant 0..3
    int o = tid & 63;        // output neuron
    int hp = v >> 1, wp = v & 1;

    float ch = (hp + 0.5f) * 0.5f; ch = ch - floorf(ch + 0.001f) - 0.5f;
    float cw = (wp + 0.5f) * 0.5f; cw = cw - floorf(cw + 0.001f) - 0.5f;
    float inp0 = 0.5f, inp1 = 0.5f, inp2 = ch, inp3 = cw;

    float acc = b2[o];
    #pragma unroll 8
    for (int k = 0; k < 64; k++) {
        float e1 = b1[k]
                 + w1[k*4+0]*inp0 + w1[k*4+1]*inp1
                 + w1[k*4+2]*inp2 + w1[k*4+3]*inp3;
        e1 = fmaxf(e1, 0.0f);
        acc += w2[o*64 + k] * e1;
    }
    acc = fmaxf(acc, 0.0f);
    s_emb[v][o] = acc;
    __syncthreads();

    if (o < E_) {
        float a = rb[o];
        for (int k = 0; k < 64; k++) a += rw[o*64 + k] * s_emb[v][k];
        s_rt[v][o] = 1.0f / (1.0f + expf(-a));
    }
    if (o >= 8 && o < 10) {
        int k = o - 8;
        float a = ob[k];
        for (int j = 0; j < 64; j++) a += ow[k*64 + j] * s_emb[v][j];
        g_off[hp][wp][k] = a;
    }
    __syncthreads();

    float* gwc = &g_wc[0][0][0][0];
    float* gwe = &g_we[0][0][0][0];
    for (int idx = tid; idx < 4*512; idx += 256) {
        int vv = idx >> 9;
        int r  = idx & 511;
        float ac = 0.0f, ae = 0.0f;
        #pragma unroll
        for (int e = 0; e < E_; e++) {
            float rt = s_rt[vv][e];
            ac += rt * WC[e*512 + r];
            ae += rt * WE[e*512 + r];
        }
        gwc[vv*512 + r] = ac;
        gwe[vv*512 + r] = ae;
    }
}

// ---------------------------------------------------------------------------
// Main kernel: block = 512 threads = 16 warps.
//   warp ww: q = ww & 1 (w-parity), g = ww >> 1 (channel group of 8).
//   lane l handles pixel w = bx*64 + 2*l + q  (same parity across the warp,
//   so dynamic-weight reads are warp-uniform and gathers are coalesced).
// grid = (W/64, H, B).
// ---------------------------------------------------------------------------
__global__ void __launch_bounds__(512) upsample_main(
    const float* __restrict__ fused, float* __restrict__ out)
{
    __shared__ float s_wc[2][8][64];      // [q][j][c]
    __shared__ float s_we[2][64][8];      // [q][c][j]
    __shared__ float s_part[8][8][64];    // [j][g][pp]
    __shared__ float s_midf[8][64];       // [j][pp]

    const int tid = threadIdx.x;
    const int l  = tid & 31;
    const int ww = tid >> 5;
    const int q  = ww & 1;                // w parity
    const int g  = ww >> 1;               // channel group
    const int h  = blockIdx.y;
    const int b  = blockIdx.z;
    const int w  = blockIdx.x * 64 + 2 * l + q;
    const int pp = q * 32 + l;            // pixel slot within block
    const int hp = h & 1;

    // Stage dynamic weights: 512 float4s, one per thread.
    {
        const float4* srcc = (const float4*)&g_wc[hp][0][0][0];   // 256 float4
        const float4* srce = (const float4*)&g_we[hp][0][0][0];   // 256 float4
        float4* dc = (float4*)&s_wc[0][0][0];
        float4* de = (float4*)&s_we[0][0][0];
        if (tid < 256) dc[tid] = srcc[tid];
        else           de[tid - 256] = srce[tid - 256];
    }
    __syncthreads();

    // Bilinear setup (all warp-uniform except the lane-linear x)
    const float offx = g_off[hp][q][0];
    const float offy = g_off[hp][q][1];
    float px = (w + 0.5f) * 0.5f - 0.5f + offx;
    float py = (h + 0.5f) * 0.5f - 0.5f + offy;
    float x0f = floorf(px), y0f = floorf(py);
    float wx = px - x0f, wy = py - y0f;
    int x0 = (int)x0f, y0 = (int)y0f;

    bool vx0 = (x0 >= 0)     && (x0 <= WLR_ - 1);
    bool vx1 = (x0 + 1 >= 0) && (x0 + 1 <= WLR_ - 1);
    bool vy0 = (y0 >= 0)     && (y0 <= HLR_ - 1);
    bool vy1 = (y0 + 1 >= 0) && (y0 + 1 <= HLR_ - 1);

    // validity folded into weights -> unconditional clamped loads
    float w00 = (vy0 && vx0) ? (1.0f - wx) * (1.0f - wy) : 0.0f;
    float w01 = (vy0 && vx1) ? wx * (1.0f - wy)          : 0.0f;
    float w10 = (vy1 && vx0) ? (1.0f - wx) * wy          : 0.0f;
    float w11 = (vy1 && vx1) ? wx * wy                   : 0.0f;

    int xc0 = min(max(x0, 0), WLR_ - 1);
    int xc1 = min(max(x0 + 1, 0), WLR_ - 1);
    int yc0 = min(max(y0, 0), HLR_ - 1);
    int yc1 = min(max(y0 + 1, 0), HLR_ - 1);

    const float* basep = fused + ((size_t)(b * C_ + g * 8)) * (HLR_ * WLR_);

    float fea0[8];
    #pragma unroll
    for (int i = 0; i < 8; i++) {
        const float* bp = basep + (size_t)i * (HLR_ * WLR_);
        const float* r0 = bp + yc0 * WLR_;
        const float* r1 = bp + yc1 * WLR_;
        fea0[i] = r0[xc0] * w00 + r0[xc1] * w01 + r1[xc0] * w10 + r1[xc1] * w11;
    }

    // Phase 1: partial mids (8x8 matvec), weights as warp-uniform float4 LDS
    {
        const float4* wc4 = (const float4*)&s_wc[q][0][g * 8];   // stride 16 f4 per j
        float4 fa = make_float4(fea0[0], fea0[1], fea0[2], fea0[3]);
        float4 fb = make_float4(fea0[4], fea0[5], fea0[6], fea0[7]);
        #pragma unroll
        for (int j = 0; j < 8; j++) {
            float4 wa = wc4[j * 16];
            float4 wb = wc4[j * 16 + 1];
            float a = wa.x * fa.x + wa.y * fa.y + wa.z * fa.z + wa.w * fa.w
                    + wb.x * fb.x + wb.y * fb.y + wb.z * fb.z + wb.w * fb.w;
            s_part[j][g][pp] = a;
        }
    }
    __syncthreads();

    // Phase 2: reducer warps 0..7 sum partials over g for all 64 pixels
    if (ww < 8) {
        const int j = ww;
        float s0 = 0.0f, s1 = 0.0f;
        #pragma unroll
        for (int gg = 0; gg < 8; gg++) {
            s0 += s_part[j][gg][l];
            s1 += s_part[j][gg][l + 32];
        }
        s_midf[j][l]      = s0;
        s_midf[j][l + 32] = s1;
    }
    __syncthreads();

    // Phase 3: read final mids for own pixel
    float mid[8];
    #pragma unroll
    for (int j = 0; j < 8; j++) mid[j] = s_midf[j][pp];

    // Expand + residual; warp-uniform float4 weight reads
    const float4* we4 = (const float4*)&s_we[q][g * 8][0];       // 2 f4 per channel
    float4 ma = make_float4(mid[0], mid[1], mid[2], mid[3]);
    float4 mb = make_float4(mid[4], mid[5], mid[6], mid[7]);
    float* ob = out + (((size_t)(b * C_ + g * 8)) * HHR_ + h) * WHR_ + w;
    #pragma unroll
    for (int i = 0; i < 8; i++) {
        float4 ea = we4[i * 2];
        float4 eb = we4[i * 2 + 1];
        float a = fea0[i]
                + ea.x * ma.x + ea.y * ma.y + ea.z * ma.z + ea.w * ma.w
                + eb.x * mb.x + eb.y * mb.y + eb.z * mb.z + eb.w * mb.w;
        ob[(size_t)i * (HHR_ * WHR_)] = a;
    }
}

// ---------------------------------------------------------------------------
extern "C" void kernel_launch(void* const* d_in, const int* in_sizes, int n_in,
                              void* d_out, int out_size)
{
    const float* fused = (const float*)d_in[1];
    const float* WC    = (const float*)d_in[2];
    const float* WE    = (const float*)d_in[3];
    const float* w1    = (const float*)d_in[4];
    const float* b1    = (const float*)d_in[5];
    const float* w2    = (const float*)d_in[6];
    const float* b2    = (const float*)d_in[7];
    const float* rw    = (const float*)d_in[8];
    const float* rb    = (const float*)d_in[9];
    const float* ow    = (const float*)d_in[10];
    const float* ob    = (const float*)d_in[11];
    float* out = (float*)d_out;

    precompute_kernel<<<1, 256>>>(w1, b1, w2, b2, rw, rb, ow, ob, WC, WE);

    dim3 grid(WHR_ / 64, HHR_, B_);
    upsample_main<<<grid, 512>>>(fused, out);
}